// round 4
// baseline (speedup 1.0000x reference)
#include <cuda_runtime.h>

#define D    512
#define KCB  2048
#define NQ   8
#define BT   16384            // B*T = 8*2048
#define NT   16               // number of 128-wide N tiles (2048/128)
#define QOFF (BT * D)         // 8388608: start of indices in out
#define LOFF (QOFF + BT * NQ) // 8519680: loss scalar

typedef unsigned long long u64;

// ---- scratch (static device globals; no allocations) ----
static __device__ float g_residual[BT * D];      // 32 MB
static __device__ float g_rownorm[BT];           // ||r||^2 per row
static __device__ float g_cnorm[NQ * KCB];       // ||cb_k||^2 for ALL levels
static __device__ float g_pval[BT * NT];         // partial argmin values
static __device__ int   g_pidx[BT * NT];         // partial argmin indices
static __device__ float g_losspart[NQ * (BT / 8)]; // per-block loss partials

// ---------------------------------------------------------------------------
// init: residual = x, quantized(out) = 0
// ---------------------------------------------------------------------------
__global__ void init_kernel(const float* __restrict__ x, float* __restrict__ out) {
    int i = blockIdx.x * blockDim.x + threadIdx.x;
    g_residual[i] = x[i];
    out[i] = 0.0f;
}

// one warp per row: rownorm = sum(r*r)
__global__ void rownorm_kernel() {
    int row  = blockIdx.x * 8 + (threadIdx.x >> 5);
    int lane = threadIdx.x & 31;
    const float* r = g_residual + row * D;
    float s = 0.0f;
#pragma unroll
    for (int d = lane; d < D; d += 32) { float v = r[d]; s += v * v; }
#pragma unroll
    for (int o = 16; o; o >>= 1) s += __shfl_xor_sync(0xffffffffu, s, o);
    if (lane == 0) g_rownorm[row] = s;
}

// one warp per code, ALL levels at once: cnorm = sum(cb*cb)
__global__ void cbnorm_all_kernel(const float* __restrict__ cbs) {
    int code = blockIdx.x * 8 + (threadIdx.x >> 5);   // 0 .. NQ*KCB-1
    int lane = threadIdx.x & 31;
    const float* c = cbs + (size_t)code * D;
    float s = 0.0f;
#pragma unroll
    for (int d = lane; d < D; d += 32) { float v = c[d]; s += v * v; }
#pragma unroll
    for (int o = 16; o; o >>= 1) s += __shfl_xor_sync(0xffffffffu, s, o);
    if (lane == 0) g_cnorm[code] = s;
}

// ---------------------------------------------------------------------------
// Fused fp32 SGEMM via packed fma.rn.f32x2 (FFMA2) + partial argmin.
// CTA tile: 128(M) x 128(N), 128 threads, per-thread 16x8, 2 CTAs/SM.
// B is stored PRE-DUPLICATED in smem ({b,b} per value, STS.64 at staging),
// so the inner loop is pure LDS.128 + FFMA2 (no per-kk movs).
// Per-lane arithmetic: IEEE fp32 FMA, k ascending 0..511 per accumulator
// (bit-identical to R1/R3 => identical indices).
// d_k = (A - 2*e_k) + c_k ; argmin strict-<, ascending k.
// ---------------------------------------------------------------------------
__global__ __launch_bounds__(128, 2) void gemm_argmin_kernel(const float* __restrict__ cb, int level) {
    __shared__ union {
        struct { float As[2][8][128]; float Bd[2][8][256]; } g; // 24 KB
        struct { float sval[128][16]; int sidx[128][16]; } e;   // 16 KB
    } sm;

    const int tid   = threadIdx.x;
    const int mBase = blockIdx.x * 128;
    const int nBase = blockIdx.y * 128;
    const int tx = tid & 15;        // N subtile  (cols tx*8 .. +8)
    const int ty = tid >> 4;        // M subtile  (rows ty*16 .. +16)

    u64 acc[8][8];                  // [i-pair][j] : rows (2p,2p+1), col j
#pragma unroll
    for (int p = 0; p < 8; p++)
#pragma unroll
        for (int j = 0; j < 8; j++) acc[p][j] = 0ull;

    // staging: thread tid loads A row (mBase+tid) and B row (nBase+tid).
    const float* Ag = g_residual + (size_t)(mBase + tid) * D;
    const float* Bg = cb        + (size_t)(nBase + tid) * D;

#define STAGE_A(st, f4, c0) {                       \
        sm.g.As[st][(c0) + 0][tid] = (f4).x;        \
        sm.g.As[st][(c0) + 1][tid] = (f4).y;        \
        sm.g.As[st][(c0) + 2][tid] = (f4).z;        \
        sm.g.As[st][(c0) + 3][tid] = (f4).w; }
#define STAGE_B1(st, c, v) {                        \
        u64 w;                                      \
        asm("mov.b64 %0, {%1, %1};" : "=l"(w) : "f"(v)); \
        *(u64*)&sm.g.Bd[st][c][2 * tid] = w; }
#define STAGE_B(st, f4, c0) {                       \
        STAGE_B1(st, (c0) + 0, (f4).x);             \
        STAGE_B1(st, (c0) + 1, (f4).y);             \
        STAGE_B1(st, (c0) + 2, (f4).z);             \
        STAGE_B1(st, (c0) + 3, (f4).w); }

    // prologue: stage 0
    {
        float4 a0 = *(const float4*)(Ag + 0);
        float4 a1 = *(const float4*)(Ag + 4);
        float4 b0 = *(const float4*)(Bg + 0);
        float4 b1 = *(const float4*)(Bg + 4);
        STAGE_A(0, a0, 0); STAGE_A(0, a1, 4);
        STAGE_B(0, b0, 0); STAGE_B(0, b1, 4);
    }
    __syncthreads();

    for (int kt = 1; kt <= 64; ++kt) {
        const int cur = (kt - 1) & 1;
        const int nxt = kt & 1;
        float4 a0, a1, b0, b1;
        if (kt < 64) {
            a0 = *(const float4*)(Ag + kt * 8);
            a1 = *(const float4*)(Ag + kt * 8 + 4);
            b0 = *(const float4*)(Bg + kt * 8);
            b1 = *(const float4*)(Bg + kt * 8 + 4);
        }
#pragma unroll
        for (int kk = 0; kk < 8; ++kk) {
            // A: 16 consecutive rows -> 8 u64 pairs (4x LDS.128, warp-broadcast)
            u64 a8[8];
            const u64* ap = (const u64*)&sm.g.As[cur][kk][ty * 16];
#pragma unroll
            for (int p = 0; p < 8; p++) a8[p] = ap[p];
            // B: 8 pre-duplicated pairs (4x LDS.128)
            u64 bd[8];
            const u64* bp = (const u64*)&sm.g.Bd[cur][kk][tx * 16];
#pragma unroll
            for (int j = 0; j < 8; j++) bd[j] = bp[j];
#pragma unroll
            for (int p = 0; p < 8; p++)
#pragma unroll
                for (int j = 0; j < 8; j++)
                    asm("fma.rn.f32x2 %0, %1, %2, %0;"
                        : "+l"(acc[p][j]) : "l"(a8[p]), "l"(bd[j]));
        }
        if (kt < 64) {
            STAGE_A(nxt, a0, 0); STAGE_A(nxt, a1, 4);
            STAGE_B(nxt, b0, 0); STAGE_B(nxt, b1, 4);
        }
        __syncthreads();
    }
    // (last __syncthreads guarantees all smem GEMM reads done before union reuse)

    // epilogue: per-thread argmin over its 8 cols, 16 rows (ascending j, strict <)
    float An[16], cn[8];
#pragma unroll
    for (int i = 0; i < 16; i++) An[i] = g_rownorm[mBase + ty * 16 + i];
#pragma unroll
    for (int j = 0; j < 8; j++) cn[j] = g_cnorm[level * KCB + nBase + tx * 8 + j];

#pragma unroll
    for (int i = 0; i < 16; i++) {
        float bvv = 3.0e38f;
        int   bj = 0;
#pragma unroll
        for (int j = 0; j < 8; j++) {
            float lo, hi;
            asm("mov.b64 {%0, %1}, %2;" : "=f"(lo), "=f"(hi) : "l"(acc[i >> 1][j]));
            float e = (i & 1) ? hi : lo;
            float dv = (An[i] - 2.0f * e) + cn[j];
            if (dv < bvv) { bvv = dv; bj = j; }
        }
        sm.e.sval[ty * 16 + i][tx] = bvv;
        sm.e.sidx[ty * 16 + i][tx] = nBase + tx * 8 + bj;
    }
    __syncthreads();

    // 16 -> 1 reduce per row (ascending tx, strict <), 128 threads = 128 rows
    {
        float bvv = sm.e.sval[tid][0];
        int   bi  = sm.e.sidx[tid][0];
#pragma unroll
        for (int t = 1; t < 16; t++) {
            float v = sm.e.sval[tid][t];
            if (v < bvv) { bvv = v; bi = sm.e.sidx[tid][t]; }
        }
        int row = mBase + tid;
        g_pval[row * NT + blockIdx.y] = bvv;
        g_pidx[row * NT + blockIdx.y] = bi;
    }
#undef STAGE_A
#undef STAGE_B1
#undef STAGE_B
}

// ---------------------------------------------------------------------------
// update: final argmin across N-tiles, gather code, quantized += q,
// residual -= q, rownorm(next) = loss partial = sum((r-q)^2)
// ---------------------------------------------------------------------------
__global__ void update_kernel(const float* __restrict__ cb, float* __restrict__ out, int level) {
    __shared__ float bsum[8];
    const int wid  = threadIdx.x >> 5;
    const int row  = blockIdx.x * 8 + wid;
    const int lane = threadIdx.x & 31;

    int idx = 0;
    if (lane == 0) {
        float bv = g_pval[row * NT];
        int   bi = g_pidx[row * NT];
#pragma unroll
        for (int t = 1; t < NT; t++) {
            float v = g_pval[row * NT + t];
            if (v < bv) { bv = v; bi = g_pidx[row * NT + t]; }
        }
        idx = bi;
        out[QOFF + row * NQ + level] = (float)bi;   // indices as f32 values
    }
    idx = __shfl_sync(0xffffffffu, idx, 0);

    const float* c = cb + (size_t)idx * D;
    float* r = g_residual + (size_t)row * D;
    float* q = out + (size_t)row * D;

    float s = 0.0f;
#pragma unroll
    for (int d = lane; d < D; d += 32) {
        float cv = c[d];
        float rv = r[d];
        q[d] += cv;               // quantized accumulates in level order
        float nr = rv - cv;       // new residual (= r_before - q_lvl)
        r[d] = nr;
        s += nr * nr;             // commit/codebook loss term & next rownorm
    }
#pragma unroll
    for (int o = 16; o; o >>= 1) s += __shfl_xor_sync(0xffffffffu, s, o);
    if (lane == 0) { g_rownorm[row] = s; bsum[wid] = s; }
    __syncthreads();
    if (threadIdx.x == 0) {
        float t = 0.0f;
#pragma unroll
        for (int w = 0; w < 8; w++) t += bsum[w];
        g_losspart[level * (BT / 8) + blockIdx.x] = t;
    }
}

// straight-through estimator rounding: out = x + (quantized - x)  (matches ref)
__global__ void ste_kernel(const float* __restrict__ x, float* __restrict__ out) {
    int i = blockIdx.x * blockDim.x + threadIdx.x;
    float xv = x[i];
    out[i] = xv + (out[i] - xv);
}

// deterministic loss reduce:  loss = 1.25 * sum / (B*T*D) / NQ
__global__ void finalize_kernel(float* __restrict__ out) {
    __shared__ float sb[256];
    float s = 0.0f;
    for (int i = threadIdx.x; i < NQ * (BT / 8); i += 256) s += g_losspart[i];
    sb[threadIdx.x] = s;
    __syncthreads();
    for (int o = 128; o; o >>= 1) {
        if (threadIdx.x < o) sb[threadIdx.x] += sb[threadIdx.x + o];
        __syncthreads();
    }
    if (threadIdx.x == 0)
        out[LOFF] = sb[0] * (0.25f + 1.0f) / (8388608.0f * (float)NQ);
}

// ---------------------------------------------------------------------------
extern "C" void kernel_launch(void* const* d_in, const int* in_sizes, int n_in,
                              void* d_out, int out_size) {
    const float* x   = (const float*)d_in[0];
    const float* cbs = (const float*)d_in[1];
    float* out = (float*)d_out;

    init_kernel<<<(BT * D) / 256, 256>>>(x, out);
    rownorm_kernel<<<BT / 8, 256>>>();
    cbnorm_all_kernel<<<(NQ * KCB) / 8, 256>>>(cbs);

    for (int q = 0; q < NQ; ++q) {
        const float* cb = cbs + (size_t)q * KCB * D;
        dim3 grid(BT / 128, KCB / 128);
        gemm_argmin_kernel<<<grid, 128>>>(cb, q);
        update_kernel<<<BT / 8, 256>>>(cb, out, q);
    }

    ste_kernel<<<(BT * D) / 256, 256>>>(x, out);
    finalize_kernel<<<1, 256>>>(out);
}

// round 6
// speedup vs baseline: 3.0098x; 3.0098x over previous
#include <cuda_runtime.h>

#define D    512
#define KCB  2048
#define NQ   8
#define BT   16384            // B*T = 8*2048
#define NT   16               // number of 128-wide N tiles (2048/128)
#define QOFF (BT * D)         // 8388608: start of indices in out
#define LOFF (QOFF + BT * NQ) // 8519680: loss scalar

typedef unsigned long long u64;

// ---- scratch (static device globals; no allocations) ----
static __device__ float g_residual[BT * D];      // 32 MB
static __device__ float g_rownorm[BT];           // ||r||^2 per row
static __device__ float g_cnorm[NQ * KCB];       // ||cb_k||^2 for ALL levels
static __device__ float g_pval[BT * NT];         // partial argmin values
static __device__ int   g_pidx[BT * NT];         // partial argmin indices
static __device__ float g_losspart[NQ * (BT / 8)]; // per-block loss partials

// ---------------------------------------------------------------------------
__global__ void init_kernel(const float* __restrict__ x, float* __restrict__ out) {
    int i = blockIdx.x * blockDim.x + threadIdx.x;
    g_residual[i] = x[i];
    out[i] = 0.0f;
}

// one warp per row: rownorm = sum(r*r)
__global__ void rownorm_kernel() {
    int row  = blockIdx.x * 8 + (threadIdx.x >> 5);
    int lane = threadIdx.x & 31;
    const float* r = g_residual + row * D;
    float s = 0.0f;
#pragma unroll
    for (int d = lane; d < D; d += 32) { float v = r[d]; s += v * v; }
#pragma unroll
    for (int o = 16; o; o >>= 1) s += __shfl_xor_sync(0xffffffffu, s, o);
    if (lane == 0) g_rownorm[row] = s;
}

// one warp per code, ALL levels at once: cnorm = sum(cb*cb)
__global__ void cbnorm_all_kernel(const float* __restrict__ cbs) {
    int code = blockIdx.x * 8 + (threadIdx.x >> 5);   // 0 .. NQ*KCB-1
    int lane = threadIdx.x & 31;
    const float* c = cbs + (size_t)code * D;
    float s = 0.0f;
#pragma unroll
    for (int d = lane; d < D; d += 32) { float v = c[d]; s += v * v; }
#pragma unroll
    for (int o = 16; o; o >>= 1) s += __shfl_xor_sync(0xffffffffu, s, o);
    if (lane == 0) g_cnorm[code] = s;
}

// ---------------------------------------------------------------------------
// Fused fp32 SGEMM via packed fma.rn.f32x2 (FFMA2) + partial argmin.
// CTA tile: 128(M) x 128(N), 128 threads, per-thread 16x8, 2 CTAs/SM.
// B pre-duplicated {b,b} in smem with XOR-swizzled layout:
//   Bd[stage][kk][g][p] (ulonglong2), read at p = tx ^ (g<<2)
//   -> every 8-lane LDS.128 phase hits all 8 bank groups: conflict-free.
// Inner loop: pure LDS.128 + FFMA2. Per-lane IEEE fp32 FMA, k ascending
// 0..511 per accumulator => indices bit-identical to R1/R3.
// d_k = (A - 2*e_k) + c_k ; argmin strict-<, ascending k.
// ---------------------------------------------------------------------------
__global__ __launch_bounds__(128, 2) void gemm_argmin_kernel(const float* __restrict__ cb, int level) {
    __shared__ union {
        struct { float As[2][8][128]; ulonglong2 Bd[2][8][4][16]; } g; // 8KB + 16KB
        struct { float sval[128][16]; int sidx[128][16]; } e;          // 16KB
    } sm;

    const int tid   = threadIdx.x;
    const int mBase = blockIdx.x * 128;
    const int nBase = blockIdx.y * 128;
    const int tx = tid & 15;        // N subtile  (cols tx*8 .. +8)
    const int ty = tid >> 4;        // M subtile  (rows ty*16 .. +16)

    u64 acc[8][8];                  // [i-pair][j] : rows (2p,2p+1), col j
#pragma unroll
    for (int p = 0; p < 8; p++)
#pragma unroll
        for (int j = 0; j < 8; j++) acc[p][j] = 0ull;

    // staging roles: thread tid loads A row (mBase+tid) and B row (nBase+tid).
    const float* Ag = g_residual + (size_t)(mBase + tid) * D;
    const float* Bg = cb        + (size_t)(nBase + tid) * D;

    // B-store coords for this thread's column n_loc = tid:
    const int txo   = tid >> 3;          // owner tx
    const int jj    = tid & 7;           // column-within-subtile
    const int gB    = jj >> 1;           // which ulonglong2 group
    const int halfB = jj & 1;            // which u64 half
    const int pB    = txo ^ (gB << 2);   // swizzled slot

#define STAGE_A(st, f4, c0) {                       \
        sm.g.As[st][(c0) + 0][tid] = (f4).x;        \
        sm.g.As[st][(c0) + 1][tid] = (f4).y;        \
        sm.g.As[st][(c0) + 2][tid] = (f4).z;        \
        sm.g.As[st][(c0) + 3][tid] = (f4).w; }
#define STAGE_B1(st, kk, v) {                       \
        u64 w;                                      \
        asm("mov.b64 %0, {%1, %1};" : "=l"(w) : "f"(v)); \
        *((u64*)&sm.g.Bd[st][kk][gB][pB] + halfB) = w; }
#define STAGE_B(st, f4, k0) {                       \
        STAGE_B1(st, (k0) + 0, (f4).x);             \
        STAGE_B1(st, (k0) + 1, (f4).y);             \
        STAGE_B1(st, (k0) + 2, (f4).z);             \
        STAGE_B1(st, (k0) + 3, (f4).w); }

    // prologue: stage 0
    {
        float4 a0 = *(const float4*)(Ag + 0);
        float4 a1 = *(const float4*)(Ag + 4);
        float4 b0 = *(const float4*)(Bg + 0);
        float4 b1 = *(const float4*)(Bg + 4);
        STAGE_A(0, a0, 0); STAGE_A(0, a1, 4);
        STAGE_B(0, b0, 0); STAGE_B(0, b1, 4);
    }
    __syncthreads();

    for (int kt = 1; kt <= 64; ++kt) {
        const int cur = (kt - 1) & 1;
        const int nxt = kt & 1;
        float4 a0, a1, b0, b1;
        if (kt < 64) {
            a0 = *(const float4*)(Ag + kt * 8);
            a1 = *(const float4*)(Ag + kt * 8 + 4);
            b0 = *(const float4*)(Bg + kt * 8);
            b1 = *(const float4*)(Bg + kt * 8 + 4);
        }
#pragma unroll
        for (int kk = 0; kk < 8; ++kk) {
            // A: 16 consecutive rows -> 8 u64 pairs (4x LDS.128, broadcast)
            u64 a8[8];
            const u64* ap = (const u64*)&sm.g.As[cur][kk][ty * 16];
#pragma unroll
            for (int p = 0; p < 8; p++) a8[p] = ap[p];
            // B: 4 conflict-free LDS.128 of pre-duplicated pairs
            u64 bd[8];
#pragma unroll
            for (int g = 0; g < 4; g++) {
                ulonglong2 q = sm.g.Bd[cur][kk][g][tx ^ (g << 2)];
                bd[2 * g]     = q.x;   // column tx*8 + 2g
                bd[2 * g + 1] = q.y;   // column tx*8 + 2g + 1
            }
#pragma unroll
            for (int p = 0; p < 8; p++)
#pragma unroll
                for (int j = 0; j < 8; j++)
                    asm("fma.rn.f32x2 %0, %1, %2, %0;"
                        : "+l"(acc[p][j]) : "l"(a8[p]), "l"(bd[j]));
        }
        if (kt < 64) {
            STAGE_A(nxt, a0, 0); STAGE_A(nxt, a1, 4);
            STAGE_B(nxt, b0, 0); STAGE_B(nxt, b1, 4);
        }
        __syncthreads();
    }
    // (last __syncthreads guarantees all smem GEMM reads done before union reuse)

    // epilogue: per-thread argmin over its 8 cols, 16 rows (ascending j, strict <)
    float An[16], cn[8];
#pragma unroll
    for (int i = 0; i < 16; i++) An[i] = g_rownorm[mBase + ty * 16 + i];
#pragma unroll
    for (int j = 0; j < 8; j++) cn[j] = g_cnorm[level * KCB + nBase + tx * 8 + j];

#pragma unroll
    for (int i = 0; i < 16; i++) {
        float bvv = 3.0e38f;
        int   bj = 0;
#pragma unroll
        for (int j = 0; j < 8; j++) {
            float lo, hi;
            asm("mov.b64 {%0, %1}, %2;" : "=f"(lo), "=f"(hi) : "l"(acc[i >> 1][j]));
            float e = (i & 1) ? hi : lo;
            float dv = (An[i] - 2.0f * e) + cn[j];
            if (dv < bvv) { bvv = dv; bj = j; }
        }
        sm.e.sval[ty * 16 + i][tx] = bvv;
        sm.e.sidx[ty * 16 + i][tx] = nBase + tx * 8 + bj;
    }
    __syncthreads();

    // 16 -> 1 reduce per row (ascending tx, strict <), 128 threads = 128 rows
    {
        float bvv = sm.e.sval[tid][0];
        int   bi  = sm.e.sidx[tid][0];
#pragma unroll
        for (int t = 1; t < 16; t++) {
            float v = sm.e.sval[tid][t];
            if (v < bvv) { bvv = v; bi = sm.e.sidx[tid][t]; }
        }
        int row = mBase + tid;
        g_pval[row * NT + blockIdx.y] = bvv;
        g_pidx[row * NT + blockIdx.y] = bi;
    }
#undef STAGE_A
#undef STAGE_B1
#undef STAGE_B
}

// ---------------------------------------------------------------------------
// update: final argmin across N-tiles, gather code, quantized += q,
// residual -= q, rownorm(next) = loss partial = sum((r-q)^2)
// ---------------------------------------------------------------------------
__global__ void update_kernel(const float* __restrict__ cb, float* __restrict__ out, int level) {
    __shared__ float bsum[8];
    const int wid  = threadIdx.x >> 5;
    const int row  = blockIdx.x * 8 + wid;
    const int lane = threadIdx.x & 31;

    int idx = 0;
    if (lane == 0) {
        float bv = g_pval[row * NT];
        int   bi = g_pidx[row * NT];
#pragma unroll
        for (int t = 1; t < NT; t++) {
            float v = g_pval[row * NT + t];
            if (v < bv) { bv = v; bi = g_pidx[row * NT + t]; }
        }
        idx = bi;
        out[QOFF + row * NQ + level] = (float)bi;   // indices as f32 values
    }
    idx = __shfl_sync(0xffffffffu, idx, 0);

    const float* c = cb + (size_t)idx * D;
    float* r = g_residual + (size_t)row * D;
    float* q = out + (size_t)row * D;

    float s = 0.0f;
#pragma unroll
    for (int d = lane; d < D; d += 32) {
        float cv = c[d];
        float rv = r[d];
        q[d] += cv;               // quantized accumulates in level order
        float nr = rv - cv;       // new residual (= r_before - q_lvl)
        r[d] = nr;
        s += nr * nr;             // commit/codebook loss term & next rownorm
    }
#pragma unroll
    for (int o = 16; o; o >>= 1) s += __shfl_xor_sync(0xffffffffu, s, o);
    if (lane == 0) { g_rownorm[row] = s; bsum[wid] = s; }
    __syncthreads();
    if (threadIdx.x == 0) {
        float t = 0.0f;
#pragma unroll
        for (int w = 0; w < 8; w++) t += bsum[w];
        g_losspart[level * (BT / 8) + blockIdx.x] = t;
    }
}

// straight-through estimator rounding: out = x + (quantized - x)  (matches ref)
__global__ void ste_kernel(const float* __restrict__ x, float* __restrict__ out) {
    int i = blockIdx.x * blockDim.x + threadIdx.x;
    float xv = x[i];
    out[i] = xv + (out[i] - xv);
}

// deterministic loss reduce:  loss = 1.25 * sum / (B*T*D) / NQ
__global__ void finalize_kernel(float* __restrict__ out) {
    __shared__ float sb[256];
    float s = 0.0f;
    for (int i = threadIdx.x; i < NQ * (BT / 8); i += 256) s += g_losspart[i];
    sb[threadIdx.x] = s;
    __syncthreads();
    for (int o = 128; o; o >>= 1) {
        if (threadIdx.x < o) sb[threadIdx.x] += sb[threadIdx.x + o];
        __syncthreads();
    }
    if (threadIdx.x == 0)
        out[LOFF] = sb[0] * (0.25f + 1.0f) / (8388608.0f * (float)NQ);
}

// ---------------------------------------------------------------------------
extern "C" void kernel_launch(void* const* d_in, const int* in_sizes, int n_in,
                              void* d_out, int out_size) {
    const float* x   = (const float*)d_in[0];
    const float* cbs = (const float*)d_in[1];
    float* out = (float*)d_out;

    init_kernel<<<(BT * D) / 256, 256>>>(x, out);
    rownorm_kernel<<<BT / 8, 256>>>();
    cbnorm_all_kernel<<<(NQ * KCB) / 8, 256>>>(cbs);

    for (int q = 0; q < NQ; ++q) {
        const float* cb = cbs + (size_t)q * KCB * D;
        dim3 grid(BT / 128, KCB / 128);
        gemm_argmin_kernel<<<grid, 128>>>(cb, q);
        update_kernel<<<BT / 8, 256>>>(cb, out, q);
    }

    ste_kernel<<<(BT * D) / 256, 256>>>(x, out);
    finalize_kernel<<<1, 256>>>(out);
}

// round 7
// speedup vs baseline: 3.6163x; 1.2015x over previous
#include <cuda_runtime.h>

#define D    512
#define KCB  2048
#define NQ   8
#define BT   16384            // B*T = 8*2048
#define NT   16               // number of 128-wide N tiles (2048/128)
#define QOFF (BT * D)         // 8388608: start of indices in out
#define LOFF (QOFF + BT * NQ) // 8519680: loss scalar

typedef unsigned long long u64;

// ---- scratch (static device globals; no allocations) ----
static __device__ float g_residual[BT * D];      // 32 MB
static __device__ float g_rownorm[BT];           // ||r||^2 per row
static __device__ float g_cnorm[NQ * KCB];       // ||cb_k||^2 for ALL levels
static __device__ float g_pval[BT * NT];         // partial argmin values
static __device__ int   g_pidx[BT * NT];         // partial argmin indices
static __device__ float g_losspart[NQ * (BT / 8)]; // per-block loss partials

// ---------------------------------------------------------------------------
__global__ void init_kernel(const float* __restrict__ x, float* __restrict__ out) {
    int i = blockIdx.x * blockDim.x + threadIdx.x;
    g_residual[i] = x[i];
    out[i] = 0.0f;
}

// one warp per row: rownorm = sum(r*r)   (accumulation order preserved)
__global__ void rownorm_kernel() {
    int row  = blockIdx.x * 8 + (threadIdx.x >> 5);
    int lane = threadIdx.x & 31;
    const float* r = g_residual + row * D;
    float s = 0.0f;
#pragma unroll
    for (int d = lane; d < D; d += 32) { float v = r[d]; s += v * v; }
#pragma unroll
    for (int o = 16; o; o >>= 1) s += __shfl_xor_sync(0xffffffffu, s, o);
    if (lane == 0) g_rownorm[row] = s;
}

// one warp per code, ALL levels at once: cnorm = sum(cb*cb)
__global__ void cbnorm_all_kernel(const float* __restrict__ cbs) {
    int code = blockIdx.x * 8 + (threadIdx.x >> 5);   // 0 .. NQ*KCB-1
    int lane = threadIdx.x & 31;
    const float* c = cbs + (size_t)code * D;
    float s = 0.0f;
#pragma unroll
    for (int d = lane; d < D; d += 32) { float v = c[d]; s += v * v; }
#pragma unroll
    for (int o = 16; o; o >>= 1) s += __shfl_xor_sync(0xffffffffu, s, o);
    if (lane == 0) g_cnorm[code] = s;
}

// ---------------------------------------------------------------------------
// Fused fp32 SGEMM via packed fma.rn.f32x2 (FFMA2) + partial argmin.
// CTA tile: 128(M) x 128(N), 128 threads, per-thread 16x8, 2 CTAs/SM.
// A packed rows (natural u64 pairs); B stored ONCE (scalar) with a word-level
// XOR swizzle (16B word w -> w ^ ((w>>3)&1)) making both B LDS.128 reads
// conflict-free; B duplicated into {b,b} register pairs via mov.b64 per kk.
// Per SM per kk: LDS = 192 wf-cycles < FFMA2 = 256 cycles -> FMA-bound.
// Per-lane IEEE fp32 FMA, k ascending 0..511 per accumulator
// => indices bit-identical to R1/R3.
// d_k = (A - 2*e_k) + c_k ; argmin strict-<, ascending k.
// ---------------------------------------------------------------------------
__global__ __launch_bounds__(128, 2) void gemm_argmin_kernel(const float* __restrict__ cb, int level) {
    __shared__ union {
        struct { float As[2][8][128]; float Bs[2][8][128]; } g; // 16 KB
        struct { float sval[128][16]; int sidx[128][16]; } e;   // 16 KB
    } sm;

    const int tid   = threadIdx.x;
    const int mBase = blockIdx.x * 128;
    const int nBase = blockIdx.y * 128;
    const int tx = tid & 15;        // N subtile  (cols tx*8 .. +8)
    const int ty = tid >> 4;        // M subtile  (rows ty*16 .. +16)

    u64 acc[8][8];                  // [i-pair][j] : rows (2p,2p+1), col j
#pragma unroll
    for (int p = 0; p < 8; p++)
#pragma unroll
        for (int j = 0; j < 8; j++) acc[p][j] = 0ull;

    // staging roles: thread tid loads A row (mBase+tid) and B row (nBase+tid).
    const float* Ag = g_residual + (size_t)(mBase + tid) * D;
    const float* Bg = cb        + (size_t)(nBase + tid) * D;

    // B store position for column tid: word (tid>>2) swizzled, float (tid&3)
    const int swS = (((tid >> 2) ^ ((tid >> 5) & 1)) << 2) + (tid & 3);
    // B load word positions for this thread's two LDS.128 (cols tx*8, tx*8+4)
    const int w0 = 2 * tx,      sw0 = (w0 ^ ((w0 >> 3) & 1)) << 2;  // float idx
    const int w1 = 2 * tx + 1,  sw1 = (w1 ^ ((w1 >> 3) & 1)) << 2;

#define STAGE_A(st, f4, c0) {                       \
        sm.g.As[st][(c0) + 0][tid] = (f4).x;        \
        sm.g.As[st][(c0) + 1][tid] = (f4).y;        \
        sm.g.As[st][(c0) + 2][tid] = (f4).z;        \
        sm.g.As[st][(c0) + 3][tid] = (f4).w; }
#define STAGE_B(st, f4, k0) {                       \
        sm.g.Bs[st][(k0) + 0][swS] = (f4).x;        \
        sm.g.Bs[st][(k0) + 1][swS] = (f4).y;        \
        sm.g.Bs[st][(k0) + 2][swS] = (f4).z;        \
        sm.g.Bs[st][(k0) + 3][swS] = (f4).w; }

    // prologue: stage 0
    {
        float4 a0 = *(const float4*)(Ag + 0);
        float4 a1 = *(const float4*)(Ag + 4);
        float4 b0 = *(const float4*)(Bg + 0);
        float4 b1 = *(const float4*)(Bg + 4);
        STAGE_A(0, a0, 0); STAGE_A(0, a1, 4);
        STAGE_B(0, b0, 0); STAGE_B(0, b1, 4);
    }
    __syncthreads();

    for (int kt = 1; kt <= 64; ++kt) {
        const int cur = (kt - 1) & 1;
        const int nxt = kt & 1;
        float4 a0, a1, b0, b1;
        if (kt < 64) {
            a0 = *(const float4*)(Ag + kt * 8);
            a1 = *(const float4*)(Ag + kt * 8 + 4);
            b0 = *(const float4*)(Bg + kt * 8);
            b1 = *(const float4*)(Bg + kt * 8 + 4);
        }
#pragma unroll
        for (int kk = 0; kk < 8; ++kk) {
            // A: 16 consecutive rows -> 8 u64 pairs (4x LDS.128, broadcast)
            u64 a8[8];
            const u64* ap = (const u64*)&sm.g.As[cur][kk][ty * 16];
#pragma unroll
            for (int p = 0; p < 8; p++) a8[p] = ap[p];
            // B: 2 conflict-free LDS.128 (swizzled words), then dup to pairs
            float bv[8];
            *(float4*)&bv[0] = *(const float4*)&sm.g.Bs[cur][kk][sw0];
            *(float4*)&bv[4] = *(const float4*)&sm.g.Bs[cur][kk][sw1];
            u64 bd[8];
#pragma unroll
            for (int j = 0; j < 8; j++)
                asm("mov.b64 %0, {%1, %1};" : "=l"(bd[j]) : "f"(bv[j]));
#pragma unroll
            for (int p = 0; p < 8; p++)
#pragma unroll
                for (int j = 0; j < 8; j++)
                    asm("fma.rn.f32x2 %0, %1, %2, %0;"
                        : "+l"(acc[p][j]) : "l"(a8[p]), "l"(bd[j]));
        }
        if (kt < 64) {
            STAGE_A(nxt, a0, 0); STAGE_A(nxt, a1, 4);
            STAGE_B(nxt, b0, 0); STAGE_B(nxt, b1, 4);
        }
        __syncthreads();
    }
    // (last __syncthreads guarantees all smem GEMM reads done before union reuse)

    // epilogue: per-thread argmin over its 8 cols, 16 rows (ascending j, strict <)
    float An[16], cn[8];
#pragma unroll
    for (int i = 0; i < 16; i++) An[i] = g_rownorm[mBase + ty * 16 + i];
#pragma unroll
    for (int j = 0; j < 8; j++) cn[j] = g_cnorm[level * KCB + nBase + tx * 8 + j];

#pragma unroll
    for (int i = 0; i < 16; i++) {
        float bvv = 3.0e38f;
        int   bj = 0;
#pragma unroll
        for (int j = 0; j < 8; j++) {
            float lo, hi;
            asm("mov.b64 {%0, %1}, %2;" : "=f"(lo), "=f"(hi) : "l"(acc[i >> 1][j]));
            float e = (i & 1) ? hi : lo;
            float dv = (An[i] - 2.0f * e) + cn[j];
            if (dv < bvv) { bvv = dv; bj = j; }
        }
        sm.e.sval[ty * 16 + i][tx] = bvv;
        sm.e.sidx[ty * 16 + i][tx] = nBase + tx * 8 + bj;
    }
    __syncthreads();

    // 16 -> 1 reduce per row (ascending tx, strict <), 128 threads = 128 rows
    {
        float bvv = sm.e.sval[tid][0];
        int   bi  = sm.e.sidx[tid][0];
#pragma unroll
        for (int t = 1; t < 16; t++) {
            float v = sm.e.sval[tid][t];
            if (v < bvv) { bvv = v; bi = sm.e.sidx[tid][t]; }
        }
        int row = mBase + tid;
        g_pval[row * NT + blockIdx.y] = bvv;
        g_pidx[row * NT + blockIdx.y] = bi;
    }
#undef STAGE_A
#undef STAGE_B
}

// ---------------------------------------------------------------------------
// update: final argmin across N-tiles, gather code, quantized += q,
// residual -= q, rownorm(next) = loss partial = sum((r-q)^2)
// ---------------------------------------------------------------------------
__global__ void update_kernel(const float* __restrict__ cb, float* __restrict__ out, int level) {
    __shared__ float bsum[8];
    const int wid  = threadIdx.x >> 5;
    const int row  = blockIdx.x * 8 + wid;
    const int lane = threadIdx.x & 31;

    int idx = 0;
    if (lane == 0) {
        float bv = g_pval[row * NT];
        int   bi = g_pidx[row * NT];
#pragma unroll
        for (int t = 1; t < NT; t++) {
            float v = g_pval[row * NT + t];
            if (v < bv) { bv = v; bi = g_pidx[row * NT + t]; }
        }
        idx = bi;
        out[QOFF + row * NQ + level] = (float)bi;   // indices as f32 values
    }
    idx = __shfl_sync(0xffffffffu, idx, 0);

    const float* c = cb + (size_t)idx * D;
    float* r = g_residual + (size_t)row * D;
    float* q = out + (size_t)row * D;

    float s = 0.0f;
#pragma unroll
    for (int d = lane; d < D; d += 32) {
        float cv = c[d];
        float rv = r[d];
        q[d] += cv;               // quantized accumulates in level order
        float nr = rv - cv;       // new residual (= r_before - q_lvl)
        r[d] = nr;
        s += nr * nr;             // commit/codebook loss term & next rownorm
    }
#pragma unroll
    for (int o = 16; o; o >>= 1) s += __shfl_xor_sync(0xffffffffu, s, o);
    if (lane == 0) { g_rownorm[row] = s; bsum[wid] = s; }
    __syncthreads();
    if (threadIdx.x == 0) {
        float t = 0.0f;
#pragma unroll
        for (int w = 0; w < 8; w++) t += bsum[w];
        g_losspart[level * (BT / 8) + blockIdx.x] = t;
    }
}

// straight-through estimator rounding: out = x + (quantized - x)  (matches ref)
__global__ void ste_kernel(const float* __restrict__ x, float* __restrict__ out) {
    int i = blockIdx.x * blockDim.x + threadIdx.x;
    float xv = x[i];
    out[i] = xv + (out[i] - xv);
}

// deterministic loss reduce:  loss = 1.25 * sum / (B*T*D) / NQ
__global__ void finalize_kernel(float* __restrict__ out) {
    __shared__ float sb[256];
    float s = 0.0f;
    for (int i = threadIdx.x; i < NQ * (BT / 8); i += 256) s += g_losspart[i];
    sb[threadIdx.x] = s;
    __syncthreads();
    for (int o = 128; o; o >>= 1) {
        if (threadIdx.x < o) sb[threadIdx.x] += sb[threadIdx.x + o];
        __syncthreads();
    }
    if (threadIdx.x == 0)
        out[LOFF] = sb[0] * (0.25f + 1.0f) / (8388608.0f * (float)NQ);
}

// ---------------------------------------------------------------------------
extern "C" void kernel_launch(void* const* d_in, const int* in_sizes, int n_in,
                              void* d_out, int out_size) {
    const float* x   = (const float*)d_in[0];
    const float* cbs = (const float*)d_in[1];
    float* out = (float*)d_out;

    init_kernel<<<(BT * D) / 256, 256>>>(x, out);
    rownorm_kernel<<<BT / 8, 256>>>();
    cbnorm_all_kernel<<<(NQ * KCB) / 8, 256>>>(cbs);

    for (int q = 0; q < NQ; ++q) {
        const float* cb = cbs + (size_t)q * KCB * D;
        dim3 grid(BT / 128, KCB / 128);
        gemm_argmin_kernel<<<grid, 128>>>(cb, q);
        update_kernel<<<BT / 8, 256>>>(cb, out, q);
    }

    ste_kernel<<<(BT * D) / 256, 256>>>(x, out);
    finalize_kernel<<<1, 256>>>(out);
}